// round 6
// baseline (speedup 1.0000x reference)
#include <cuda_runtime.h>
#include <mma.h>
#include <math.h>
#include <float.h>

using namespace nvcuda;

#define BB 8
#define NN 1024
#define KNN 20

// ---------------- static device scratch ----------------
__device__ float    g_G[(size_t)BB*NN*NN];        // pairwise 2*dot - sq[m]
__device__ float    g_SQ[BB*NN];
__device__ int      g_IDX[BB*NN*KNN];
__device__ float    g_Z2[(size_t)BB*NN*512];      // [bn][2O]: Zn | Zc ; reused as Y5
__device__ float    g_FEAT[(size_t)BB*NN*512];    // concat features (bn, c)
__device__ float    g_YMAX[(size_t)BB*NN*256];
__device__ float    g_YMIN[(size_t)BB*NN*256];
__device__ double   g_SUM[512];
__device__ double   g_SUMSQ[512];
__device__ float    g_A[512];
__device__ float    g_Cc[512];
__device__ float    g_WCAT[90496];                // [Wn ; Wc-Wn] per block
__device__ unsigned g_MXU[BB*512];
__device__ unsigned g_MNU[BB*512];

__device__ __forceinline__ unsigned encf(float f) {
    unsigned b = __float_as_uint(f);
    return (b & 0x80000000u) ? ~b : (b | 0x80000000u);
}
__device__ __forceinline__ float decf(unsigned u) {
    return __uint_as_float((u & 0x80000000u) ? (u & 0x7FFFFFFFu) : ~u);
}

// WCAT offsets: b1:0 (128x3), b2:384 (128x64), b3:8576 (256x64), b4:24960 (512x128)
__global__ void prep_kernel(const float* __restrict__ w1, const float* __restrict__ w2,
                            const float* __restrict__ w3, const float* __restrict__ w4) {
    int t = blockIdx.x * blockDim.x + threadIdx.x;
    if (t < 384) {
        int r = t/3, c = t%3;
        g_WCAT[t] = (r < 64) ? w1[r*6 + c] : (w1[(r-64)*6 + 3 + c] - w1[(r-64)*6 + c]);
        return;
    }
    int u = t - 384;
    if (u < 8192) {
        int r = u/64, c = u%64;
        g_WCAT[384 + u] = (r < 64) ? w2[r*128 + c] : (w2[(r-64)*128 + 64 + c] - w2[(r-64)*128 + c]);
        return;
    }
    u -= 8192;
    if (u < 16384) {
        int r = u/64, c = u%64;
        g_WCAT[8576 + u] = (r < 128) ? w3[r*128 + c] : (w3[(r-128)*128 + 64 + c] - w3[(r-128)*128 + c]);
        return;
    }
    u -= 16384;
    if (u < 65536) {
        int r = u/128, c = u%128;
        g_WCAT[24960 + u] = (r < 256) ? w4[r*256 + c] : (w4[(r-256)*256 + 128 + c] - w4[(r-256)*256 + c]);
        return;
    }
}

template<int C>
__global__ void sq_kernel(const float* __restrict__ X, int ld, int off) {
    int i = blockIdx.x * blockDim.x + threadIdx.x;
    if (i >= BB*NN) return;
    const float* p = X + (size_t)i*ld + off;
    float s = 0.f;
    #pragma unroll
    for (int c = 0; c < C; c++) s = fmaf(p[c], p[c], s);
    g_SQ[i] = s;
}

// =======================================================================
// Split-TF32 NT GEMM via wmma m16n16k8: OUT[r][c] = sum_k A[r][k]*B[c][k]
// acc = Ahi*Bhi + Ahi*Blo + Alo*Bhi  (~fp32 accuracy).
// MODE 0 (gram): A pre-scaled x2; one extra k-tile appends A_ext=1,
//                B_ext=-sq[brow] so OUT = 2*dot - sq[col]. Batched via bz.
// MODE 1: plain GEMM.
// Block 256 thr = 8 warps (4 along M x 2 along N); tile 128x128, k-tile 16.
// =======================================================================
template<int MODE>
__global__ void __launch_bounds__(256)
tf32gemm(const float* __restrict__ A, int lda,
         const float* __restrict__ B, int ldb,
         int K, float* __restrict__ OUT, int ldo) {
    __shared__ __align__(16) float sAhi[16][136];
    __shared__ __align__(16) float sAlo[16][136];
    __shared__ __align__(16) float sBhi[16][136];
    __shared__ __align__(16) float sBlo[16][136];

    int t    = threadIdx.x;
    int warp = t >> 5;
    int wm   = warp & 3;       // M position (4 warps)
    int wn   = warp >> 2;      // N position (2 warps)
    int bz   = blockIdx.z;

    int row0     = (MODE == 0 ? bz*1024 : 0) + blockIdx.x*128;  // A rows (global)
    int browBase = (MODE == 0 ? bz*1024 : 0) + blockIdx.y*128;  // B rows
    int colOut   = blockIdx.y*128;

    const float* Abase = A + (size_t)row0 * lda;
    const float* Bbase = B + (size_t)browBase * ldb;

    wmma::fragment<wmma::accumulator, 16, 16, 8, float> acc[2][4];
    #pragma unroll
    for (int i = 0; i < 2; i++)
        #pragma unroll
        for (int j = 0; j < 4; j++) wmma::fill_fragment(acc[i][j], 0.f);

    int KT = K/16 + (MODE == 0 ? 1 : 0);

    for (int kt = 0; kt < KT; kt++) {
        // stage k-tile [kt*16, kt*16+16) transposed into smem, split hi/lo
        #pragma unroll
        for (int rr = 0; rr < 2; rr++) {
            int f = t + rr*256;          // 0..511
            int row = f >> 2, q = f & 3;
            int kk = kt*16 + q*4;
            float4 a4, b4;
            if (MODE == 0 && kk >= K) {
                a4 = make_float4(0.f, 0.f, 0.f, 0.f);
                b4 = make_float4(0.f, 0.f, 0.f, 0.f);
                if (kk == K) {           // slot K: A_ext=1, B_ext=-sq
                    a4.x = 1.f;
                    b4.x = -g_SQ[browBase + row];
                }
            } else {
                a4 = *(const float4*)(Abase + (size_t)row*lda + kk);
                b4 = *(const float4*)(Bbase + (size_t)row*ldb + kk);
                if (MODE == 0) { a4.x *= 2.f; a4.y *= 2.f; a4.z *= 2.f; a4.w *= 2.f; }
            }
            float h;
            h = wmma::__float_to_tf32(a4.x); sAhi[q*4+0][row] = h; sAlo[q*4+0][row] = wmma::__float_to_tf32(a4.x - h);
            h = wmma::__float_to_tf32(a4.y); sAhi[q*4+1][row] = h; sAlo[q*4+1][row] = wmma::__float_to_tf32(a4.y - h);
            h = wmma::__float_to_tf32(a4.z); sAhi[q*4+2][row] = h; sAlo[q*4+2][row] = wmma::__float_to_tf32(a4.z - h);
            h = wmma::__float_to_tf32(a4.w); sAhi[q*4+3][row] = h; sAlo[q*4+3][row] = wmma::__float_to_tf32(a4.w - h);
            h = wmma::__float_to_tf32(b4.x); sBhi[q*4+0][row] = h; sBlo[q*4+0][row] = wmma::__float_to_tf32(b4.x - h);
            h = wmma::__float_to_tf32(b4.y); sBhi[q*4+1][row] = h; sBlo[q*4+1][row] = wmma::__float_to_tf32(b4.y - h);
            h = wmma::__float_to_tf32(b4.z); sBhi[q*4+2][row] = h; sBlo[q*4+2][row] = wmma::__float_to_tf32(b4.z - h);
            h = wmma::__float_to_tf32(b4.w); sBhi[q*4+3][row] = h; sBlo[q*4+3][row] = wmma::__float_to_tf32(b4.w - h);
        }
        __syncthreads();

        #pragma unroll
        for (int k8 = 0; k8 < 16; k8 += 8) {
            wmma::fragment<wmma::matrix_a, 16, 16, 8, wmma::precision::tf32, wmma::col_major> ahi[2], alo[2];
            wmma::fragment<wmma::matrix_b, 16, 16, 8, wmma::precision::tf32, wmma::row_major> bhi[4], blo[4];
            #pragma unroll
            for (int mi = 0; mi < 2; mi++) {
                wmma::load_matrix_sync(ahi[mi], &sAhi[k8][wm*32 + mi*16], 136);
                wmma::load_matrix_sync(alo[mi], &sAlo[k8][wm*32 + mi*16], 136);
            }
            #pragma unroll
            for (int ni = 0; ni < 4; ni++) {
                wmma::load_matrix_sync(bhi[ni], &sBhi[k8][wn*64 + ni*16], 136);
                wmma::load_matrix_sync(blo[ni], &sBlo[k8][wn*64 + ni*16], 136);
            }
            #pragma unroll
            for (int mi = 0; mi < 2; mi++)
                #pragma unroll
                for (int ni = 0; ni < 4; ni++) {
                    wmma::mma_sync(acc[mi][ni], ahi[mi], bhi[ni], acc[mi][ni]);
                    wmma::mma_sync(acc[mi][ni], ahi[mi], blo[ni], acc[mi][ni]);
                    wmma::mma_sync(acc[mi][ni], alo[mi], bhi[ni], acc[mi][ni]);
                }
        }
        __syncthreads();
    }

    #pragma unroll
    for (int mi = 0; mi < 2; mi++)
        #pragma unroll
        for (int ni = 0; ni < 4; ni++) {
            float* p = OUT + (size_t)(row0 + wm*32 + mi*16)*ldo + colOut + wn*64 + ni*16;
            wmma::store_matrix_sync(p, acc[mi][ni], ldo, wmma::mem_row_major);
        }
}

// ---------------- stage-1 zgemm (C=3) ----------------
template<int C, int N2>
__global__ void zgemm_kernel(const float* __restrict__ X, int ld, int off,
                             const float* __restrict__ W) {
    constexpr int TC = (C < 32) ? C : 32;
    __shared__ float As[64][TC+1];
    __shared__ float Bs[64][TC+1];
    int r0 = blockIdx.x * 64;
    int o0 = blockIdx.y * 64;
    int tx = threadIdx.x & 15, ty = threadIdx.x >> 4;
    float acc[4][4];
    #pragma unroll
    for (int i = 0; i < 4; i++)
        #pragma unroll
        for (int j = 0; j < 4; j++) acc[i][j] = 0.f;
    for (int c0 = 0; c0 < C; c0 += TC) {
        for (int i = threadIdx.x; i < 64*TC; i += 256) {
            int r = i / TC, c = i - r*TC;
            As[r][c] = X[(size_t)(r0 + r)*ld + off + c0 + c];
            Bs[r][c] = W[(size_t)(o0 + r)*C + c0 + c];
        }
        __syncthreads();
        for (int c = 0; c < TC; c++) {
            float av[4], bv[4];
            #pragma unroll
            for (int i = 0; i < 4; i++) { av[i] = As[ty*4+i][c]; bv[i] = Bs[tx*4+i][c]; }
            #pragma unroll
            for (int i = 0; i < 4; i++)
                #pragma unroll
                for (int j = 0; j < 4; j++) acc[i][j] = fmaf(av[i], bv[j], acc[i][j]);
        }
        __syncthreads();
    }
    #pragma unroll
    for (int i = 0; i < 4; i++)
        #pragma unroll
        for (int j = 0; j < 4; j++)
            g_Z2[(size_t)(r0 + ty*4 + i)*N2 + o0 + tx*4 + j] = acc[i][j];
}

// ---------------- stage-1 fused distances + top-20 ----------------
__global__ void topk1_kernel(const float* __restrict__ x) {
    __shared__ float spx[1024], spy[1024], spz[1024], ssq[1024];
    int n0 = blockIdx.x * 8;
    int b  = n0 >> 10;
    int t  = threadIdx.x;
    const float* xb = x + (size_t)b * 3072;
    for (int m = t; m < 1024; m += 256) {
        float px = xb[m*3], py = xb[m*3+1], pz = xb[m*3+2];
        spx[m] = px; spy[m] = py; spz[m] = pz;
        ssq[m] = fmaf(px, px, fmaf(py, py, pz*pz));
    }
    __syncthreads();

    int warp = t >> 5, l = t & 31;
    int ln = (n0 & 1023) + warp;
    float dnx = 2.f*spx[ln], dny = 2.f*spy[ln], dnz = 2.f*spz[ln];

    float v[32];
    #pragma unroll
    for (int s = 0; s < 32; s++) {
        int m = s*32 + l;
        v[s] = fmaf(dnx, spx[m], fmaf(dny, spy[m], fmaf(dnz, spz[m], -ssq[m])));
    }

    float m1 = -FLT_MAX, m2 = -FLT_MAX;
    int s1 = 0, s2 = 0;
    #pragma unroll
    for (int s = 0; s < 32; s++) {
        float xv = v[s];
        if (xv > m2) {
            if (xv > m1) { m2 = m1; s2 = s1; m1 = xv; s1 = s; }
            else         { m2 = xv; s2 = s; }
        }
    }
    bool dirty = false;
    int row = n0 + warp;
    for (int j = 0; j < KNN; j++) {
        float bv = m1;
        int   bm = (s1 << 5) | l;
        #pragma unroll
        for (int o = 16; o; o >>= 1) {
            float ov = __shfl_xor_sync(0xFFFFFFFFu, bv, o);
            int   om = __shfl_xor_sync(0xFFFFFFFFu, bm, o);
            if (ov > bv || (ov == bv && om < bm)) { bv = ov; bm = om; }
        }
        if (l == 0) g_IDX[row*KNN + j] = bm;
        if ((bm & 31) == l) {
            #pragma unroll
            for (int s = 0; s < 32; s++) if (s == s1) v[s] = -FLT_MAX;
            if (!dirty) { m1 = m2; s1 = s2; dirty = true; }
            else {
                m1 = -FLT_MAX; m2 = -FLT_MAX; s1 = 0; s2 = 0;
                #pragma unroll
                for (int s = 0; s < 32; s++) {
                    float xv = v[s];
                    if (xv > m2) {
                        if (xv > m1) { m2 = m1; s2 = s1; m1 = xv; s1 = s; }
                        else         { m2 = xv; s2 = s; }
                    }
                }
                dirty = false;
            }
        }
    }
}

// ---------------- top-20 from g_G (stages 2-4) ----------------
__global__ void topk_kernel() {
    int warp = (blockIdx.x << 3) + (threadIdx.x >> 5);
    int l = threadIdx.x & 31;
    const float* grow = g_G + (size_t)warp * NN;
    float v[32];
    #pragma unroll
    for (int s = 0; s < 32; s++) v[s] = grow[s*32 + l];

    float m1 = -FLT_MAX, m2 = -FLT_MAX;
    int s1 = 0, s2 = 0;
    #pragma unroll
    for (int s = 0; s < 32; s++) {
        float x = v[s];
        if (x > m2) {
            if (x > m1) { m2 = m1; s2 = s1; m1 = x; s1 = s; }
            else        { m2 = x;  s2 = s; }
        }
    }
    bool dirty = false;

    for (int j = 0; j < KNN; j++) {
        float bv = m1;
        int   bm = (s1 << 5) | l;
        #pragma unroll
        for (int o = 16; o; o >>= 1) {
            float ov = __shfl_xor_sync(0xFFFFFFFFu, bv, o);
            int   om = __shfl_xor_sync(0xFFFFFFFFu, bm, o);
            if (ov > bv || (ov == bv && om < bm)) { bv = ov; bm = om; }
        }
        if (l == 0) g_IDX[warp*KNN + j] = bm;
        if ((bm & 31) == l) {
            #pragma unroll
            for (int s = 0; s < 32; s++) if (s == s1) v[s] = -FLT_MAX;
            if (!dirty) { m1 = m2; s1 = s2; dirty = true; }
            else {
                m1 = -FLT_MAX; m2 = -FLT_MAX; s1 = 0; s2 = 0;
                #pragma unroll
                for (int s = 0; s < 32; s++) {
                    float x = v[s];
                    if (x > m2) {
                        if (x > m1) { m2 = m1; s2 = s1; m1 = x; s1 = s; }
                        else        { m2 = x;  s2 = s; }
                    }
                }
                dirty = false;
            }
        }
    }
}

// ---------------- gather + k-reduce: float4 per thread, smem stats ----------------
template<int O>
__global__ void gather_kernel() {
    constexpr int TP  = O / 4;
    constexpr int PPB = 256 / TP;
    __shared__ int   sidx[PPB*KNN];
    __shared__ float ssum[O], ssq2[O];

    int n0 = blockIdx.x * PPB;
    int b  = n0 >> 10;
    int t  = threadIdx.x;
    if (t < O) { ssum[t] = 0.f; ssq2[t] = 0.f; }
    for (int i = t; i < PPB*KNN; i += 256) sidx[i] = g_IDX[n0*KNN + i];
    __syncthreads();

    int p  = t / TP;
    int cg = (t % TP) * 4;
    int n  = n0 + p;
    const float* Zb = g_Z2 + ((size_t)b << 10) * (2*O);

    float4 ctr = *(const float4*)&g_Z2[(size_t)n*(2*O) + O + cg];
    float4 mx = {-FLT_MAX, -FLT_MAX, -FLT_MAX, -FLT_MAX};
    float4 mn = { FLT_MAX,  FLT_MAX,  FLT_MAX,  FLT_MAX};
    float4 s  = {0.f, 0.f, 0.f, 0.f};
    float4 s2 = {0.f, 0.f, 0.f, 0.f};

    #pragma unroll
    for (int j = 0; j < KNN; j++) {
        int m = sidx[p*KNN + j];
        float4 z = *(const float4*)&Zb[(size_t)m*(2*O) + cg];
        mx.x = fmaxf(mx.x, z.x); mn.x = fminf(mn.x, z.x); s.x += z.x; s2.x = fmaf(z.x, z.x, s2.x);
        mx.y = fmaxf(mx.y, z.y); mn.y = fminf(mn.y, z.y); s.y += z.y; s2.y = fmaf(z.y, z.y, s2.y);
        mx.z = fmaxf(mx.z, z.z); mn.z = fminf(mn.z, z.z); s.z += z.z; s2.z = fmaf(z.z, z.z, s2.z);
        mx.w = fmaxf(mx.w, z.w); mn.w = fminf(mn.w, z.w); s.w += z.w; s2.w = fmaf(z.w, z.w, s2.w);
    }

    float4 omx = {mx.x + ctr.x, mx.y + ctr.y, mx.z + ctr.z, mx.w + ctr.w};
    float4 omn = {mn.x + ctr.x, mn.y + ctr.y, mn.z + ctr.z, mn.w + ctr.w};
    *(float4*)&g_YMAX[(size_t)n*O + cg] = omx;
    *(float4*)&g_YMIN[(size_t)n*O + cg] = omn;

    const float KF = (float)KNN;
    atomicAdd(&ssum[cg+0], s.x + KF*ctr.x);
    atomicAdd(&ssum[cg+1], s.y + KF*ctr.y);
    atomicAdd(&ssum[cg+2], s.z + KF*ctr.z);
    atomicAdd(&ssum[cg+3], s.w + KF*ctr.w);
    atomicAdd(&ssq2[cg+0], s2.x + 2.f*ctr.x*s.x + KF*ctr.x*ctr.x);
    atomicAdd(&ssq2[cg+1], s2.y + 2.f*ctr.y*s.y + KF*ctr.y*ctr.y);
    atomicAdd(&ssq2[cg+2], s2.z + 2.f*ctr.z*s.z + KF*ctr.z*ctr.z);
    atomicAdd(&ssq2[cg+3], s2.w + 2.f*ctr.w*s.w + KF*ctr.w*ctr.w);
    __syncthreads();
    if (t < O) {
        atomicAdd(&g_SUM[t],   (double)ssum[t]);
        atomicAdd(&g_SUMSQ[t], (double)ssq2[t]);
    }
}

// ---------------- BN affine coeffs; self-resets accumulators ----------------
__global__ void stats_kernel(const float* __restrict__ g, const float* __restrict__ beta,
                             float count, int O, int resetMM) {
    int o = threadIdx.x;
    if (resetMM) {
        for (int i = o; i < BB*512; i += 512) { g_MXU[i] = 0u; g_MNU[i] = 0xFFFFFFFFu; }
    }
    if (o >= O) return;
    double m   = g_SUM[o]   / (double)count;
    double var = g_SUMSQ[o] / (double)count - m*m;
    float a = g[o] / sqrtf((float)var + 1e-5f);
    g_A[o]  = a;
    g_Cc[o] = beta[o] - (float)m * a;
    g_SUM[o] = 0.0; g_SUMSQ[o] = 0.0;
}

__global__ void apply_kernel(int O, int outOff) {
    int i = blockIdx.x * blockDim.x + threadIdx.x;
    if (i >= BB*NN*O) return;
    int o  = i % O;
    int bn = i / O;
    float a = g_A[o], c = g_Cc[o];
    float sel = (a >= 0.f) ? g_YMAX[i] : g_YMIN[i];
    float v = fmaf(a, sel, c);
    g_FEAT[(size_t)bn*512 + outOff + o] = (v >= 0.f) ? v : 0.2f*v;
}

// ---------------- gemm5 stats reduce over n per (b,o) ----------------
__global__ void reduce5_kernel() {
    int b  = blockIdx.x >> 3;
    int c0 = (blockIdx.x & 7) * 128;
    int o  = threadIdx.x;
    const float* base = g_Z2 + (size_t)(b*1024 + c0)*512 + o;
    float mx = -FLT_MAX, mn = FLT_MAX, s = 0.f, s2 = 0.f;
    #pragma unroll 4
    for (int n = 0; n < 128; n++) {
        float v = base[(size_t)n*512];
        mx = fmaxf(mx, v); mn = fminf(mn, v);
        s += v; s2 = fmaf(v, v, s2);
    }
    atomicAdd(&g_SUM[o],   (double)s);
    atomicAdd(&g_SUMSQ[o], (double)s2);
    atomicMax(&g_MXU[b*512 + o], encf(mx));
    atomicMin(&g_MNU[b*512 + o], encf(mn));
}

// ---------------- final norm + global max + embedding ----------------
__global__ void emb_kernel(const float* __restrict__ wemb, float* __restrict__ out) {
    __shared__ float feat[512];
    int b = blockIdx.x, t = threadIdx.x;
    for (int o = t; o < 512; o += 256) {
        float a = g_A[o], c = g_Cc[o];
        float sel = (a >= 0.f) ? decf(g_MXU[b*512 + o]) : decf(g_MNU[b*512 + o]);
        float v = fmaf(a, sel, c);
        feat[o] = (v >= 0.f) ? v : 0.2f*v;
    }
    __syncthreads();
    const float* wr = wemb + (size_t)t * 512;
    float s = 0.f;
    for (int c = 0; c < 512; c++) s = fmaf(wr[c], feat[c], s);
    out[b*256 + t] = s;
}

// ---------------- host orchestration ----------------
template<int C, int O>
static void run_edge_big(const float* feat, int off, const float* wcat,
                         const float* g, const float* beta, int outOff, int resetMM,
                         float* gptr, float* z2ptr) {
    sq_kernel<C><<<32, 256>>>(feat, 512, off);
    tf32gemm<0><<<dim3(8, 8, BB), 256>>>(feat + off, 512, feat + off, 512, C, gptr, 1024);
    topk_kernel<<<BB*NN/8, 256>>>();
    tf32gemm<1><<<dim3(64, (2*O)/128, 1), 256>>>(feat + off, 512, wcat, C, C, z2ptr, 2*O);
    gather_kernel<O><<<BB*NN/(256/(O/4)), 256>>>();
    stats_kernel<<<1, 512>>>(g, beta, (float)(BB*NN*KNN), O, resetMM);
    apply_kernel<<<(BB*NN*O + 255)/256, 256>>>(O, outOff);
}

extern "C" void kernel_launch(void* const* d_in, const int* in_sizes, int n_in,
                              void* d_out, int out_size) {
    (void)in_sizes; (void)n_in; (void)out_size;
    const float* x    = (const float*)d_in[0];
    const float* w1   = (const float*)d_in[1];
    const float* g1   = (const float*)d_in[2];
    const float* b1   = (const float*)d_in[3];
    const float* w2   = (const float*)d_in[4];
    const float* g2   = (const float*)d_in[5];
    const float* b2   = (const float*)d_in[6];
    const float* w3   = (const float*)d_in[7];
    const float* g3   = (const float*)d_in[8];
    const float* b3   = (const float*)d_in[9];
    const float* w4   = (const float*)d_in[10];
    const float* g4   = (const float*)d_in[11];
    const float* b4   = (const float*)d_in[12];
    const float* w5   = (const float*)d_in[13];
    const float* g5   = (const float*)d_in[14];
    const float* b5   = (const float*)d_in[15];
    const float* wemb = (const float*)d_in[16];
    float* out = (float*)d_out;

    float *feat, *wcat, *gptr, *z2ptr;
    cudaGetSymbolAddress((void**)&feat,  g_FEAT);
    cudaGetSymbolAddress((void**)&wcat,  g_WCAT);
    cudaGetSymbolAddress((void**)&gptr,  g_G);
    cudaGetSymbolAddress((void**)&z2ptr, g_Z2);

    prep_kernel<<<(90496 + 255)/256, 256>>>(w1, w2, w3, w4);

    // ---- stage 1 (C=3): fused distance + topk, small zgemm ----
    topk1_kernel<<<BB*NN/8, 256>>>(x);
    dim3 zg1(BB*NN/64, 2);
    zgemm_kernel<3, 128><<<zg1, 256>>>(x, 3, 0, wcat);
    gather_kernel<64><<<BB*NN/16, 256>>>();
    stats_kernel<<<1, 512>>>(g1, b1, (float)(BB*NN*KNN), 64, 0);
    apply_kernel<<<(BB*NN*64 + 255)/256, 256>>>(64, 0);

    // ---- stages 2-4: tensor-core path ----
    run_edge_big<64,  64 >(feat, 0,   wcat + 384,   g2, b2, 64,  0, gptr, z2ptr);
    run_edge_big<64,  128>(feat, 64,  wcat + 8576,  g3, b3, 128, 0, gptr, z2ptr);
    run_edge_big<128, 256>(feat, 128, wcat + 24960, g4, b4, 256, 1, gptr, z2ptr);

    // ---- final conv 512x512 (tf32) -> Y in g_Z2, then fused stats reduce ----
    tf32gemm<1><<<dim3(64, 4, 1), 256>>>(feat, 512, w5, 512, 512, z2ptr, 512);
    reduce5_kernel<<<64, 512>>>();
    stats_kernel<<<1, 512>>>(g5, b5, (float)(BB*NN), 512, 0);
    emb_kernel<<<BB, 256>>>(wemb, out);
}

// round 7
// speedup vs baseline: 1.6031x; 1.6031x over previous
#include <cuda_runtime.h>
#include <math.h>
#include <float.h>

#define BB 8
#define NN 1024
#define KNN 20

// ---------------- static device scratch ----------------
__device__ float    g_G[(size_t)BB*NN*NN];        // pairwise 2*dot - sq[m]
__device__ float    g_SQ[BB*NN];
__device__ int      g_IDX[BB*NN*KNN];
__device__ float    g_Z2[(size_t)BB*NN*512];      // [bn][2O]: Zn | Zc
__device__ float    g_FEAT[(size_t)BB*NN*512];    // concat features (bn, c)
__device__ float    g_YMAX[(size_t)BB*NN*256];
__device__ float    g_YMIN[(size_t)BB*NN*256];
__device__ double   g_SUM[512];
__device__ double   g_SUMSQ[512];
__device__ float    g_A[512];
__device__ float    g_Cc[512];
__device__ float    g_WCAT[90496];                // [Wn ; Wc-Wn] per block
__device__ unsigned g_MXU[BB*512];
__device__ unsigned g_MNU[BB*512];

__device__ __forceinline__ unsigned encf(float f) {
    unsigned b = __float_as_uint(f);
    return (b & 0x80000000u) ? ~b : (b | 0x80000000u);
}
__device__ __forceinline__ float decf(unsigned u) {
    return __uint_as_float((u & 0x80000000u) ? (u & 0x7FFFFFFFu) : ~u);
}

// WCAT offsets: b1:0 (128x3), b2:384 (128x64), b3:8576 (256x64), b4:24960 (512x128)
__global__ void prep_kernel(const float* __restrict__ w1, const float* __restrict__ w2,
                            const float* __restrict__ w3, const float* __restrict__ w4) {
    int t = blockIdx.x * blockDim.x + threadIdx.x;
    if (t < 384) {
        int r = t/3, c = t%3;
        g_WCAT[t] = (r < 64) ? w1[r*6 + c] : (w1[(r-64)*6 + 3 + c] - w1[(r-64)*6 + c]);
        return;
    }
    int u = t - 384;
    if (u < 8192) {
        int r = u/64, c = u%64;
        g_WCAT[384 + u] = (r < 64) ? w2[r*128 + c] : (w2[(r-64)*128 + 64 + c] - w2[(r-64)*128 + c]);
        return;
    }
    u -= 8192;
    if (u < 16384) {
        int r = u/64, c = u%64;
        g_WCAT[8576 + u] = (r < 128) ? w3[r*128 + c] : (w3[(r-128)*128 + 64 + c] - w3[(r-128)*128 + c]);
        return;
    }
    u -= 16384;
    if (u < 65536) {
        int r = u/128, c = u%128;
        g_WCAT[24960 + u] = (r < 256) ? w4[r*256 + c] : (w4[(r-256)*256 + 128 + c] - w4[(r-256)*256 + c]);
        return;
    }
}

template<int C>
__global__ void sq_kernel(const float* __restrict__ X, int ld, int off) {
    int i = blockIdx.x * blockDim.x + threadIdx.x;
    if (i >= BB*NN) return;
    const float* p = X + (size_t)i*ld + off;
    float s = 0.f;
    #pragma unroll
    for (int c = 0; c < C; c++) s = fmaf(p[c], p[c], s);
    g_SQ[i] = s;
}

// =======================================================================
// Symmetric gram (reg-prefetch pipelined): block per (i<=j) tile pair.
// =======================================================================
__global__ void __launch_bounds__(256, 2)
gram_sym(const float* __restrict__ A, int lda, int K) {
    __shared__ __align__(16) float sAs[16][132];
    __shared__ __align__(16) float sBs[16][132];

    int t  = threadIdx.x;
    int tx = t & 15, ty = t >> 4;
    int bz = blockIdx.z;

    int idx = blockIdx.x;
    int ib = 0;
    while (idx >= 8 - ib) { idx -= 8 - ib; ib++; }
    int jb = ib + idx;

    int arow0 = ib * 128;
    int brow0 = jb * 128;
    const float* Abase = A + (size_t)(bz*1024 + arow0) * lda;
    const float* Bbase = A + (size_t)(bz*1024 + brow0) * lda;

    float acc[8][8];
    #pragma unroll
    for (int i = 0; i < 8; i++)
        #pragma unroll
        for (int j = 0; j < 8; j++) acc[i][j] = 0.f;

    int lrow[2], lq[2];
    #pragma unroll
    for (int rr = 0; rr < 2; rr++) { int f = t + rr*256; lrow[rr] = f >> 2; lq[rr] = f & 3; }

    float4 va[2], vb[2];
    #pragma unroll
    for (int rr = 0; rr < 2; rr++) {
        va[rr] = *(const float4*)(Abase + (size_t)lrow[rr]*lda + lq[rr]*4);
        vb[rr] = *(const float4*)(Bbase + (size_t)lrow[rr]*lda + lq[rr]*4);
    }

    for (int kt = 0; kt < K; kt += 16) {
        #pragma unroll
        for (int rr = 0; rr < 2; rr++) {
            sAs[lq[rr]*4+0][lrow[rr]] = va[rr].x; sAs[lq[rr]*4+1][lrow[rr]] = va[rr].y;
            sAs[lq[rr]*4+2][lrow[rr]] = va[rr].z; sAs[lq[rr]*4+3][lrow[rr]] = va[rr].w;
            sBs[lq[rr]*4+0][lrow[rr]] = vb[rr].x; sBs[lq[rr]*4+1][lrow[rr]] = vb[rr].y;
            sBs[lq[rr]*4+2][lrow[rr]] = vb[rr].z; sBs[lq[rr]*4+3][lrow[rr]] = vb[rr].w;
        }
        __syncthreads();
        if (kt + 16 < K) {
            #pragma unroll
            for (int rr = 0; rr < 2; rr++) {
                va[rr] = *(const float4*)(Abase + (size_t)lrow[rr]*lda + kt + 16 + lq[rr]*4);
                vb[rr] = *(const float4*)(Bbase + (size_t)lrow[rr]*lda + kt + 16 + lq[rr]*4);
            }
        }
        #pragma unroll
        for (int k = 0; k < 16; k++) {
            float4 a0 = *(const float4*)&sAs[k][ty*8];
            float4 a1 = *(const float4*)&sAs[k][ty*8 + 4];
            float4 b0 = *(const float4*)&sBs[k][tx*8];
            float4 b1 = *(const float4*)&sBs[k][tx*8 + 4];
            float av[8] = {a0.x, a0.y, a0.z, a0.w, a1.x, a1.y, a1.z, a1.w};
            float bv[8] = {b0.x, b0.y, b0.z, b0.w, b1.x, b1.y, b1.z, b1.w};
            #pragma unroll
            for (int i = 0; i < 8; i++)
                #pragma unroll
                for (int j = 0; j < 8; j++) acc[i][j] = fmaf(av[i], bv[j], acc[i][j]);
        }
        __syncthreads();
    }

    float sqa[8], sqb[8];
    #pragma unroll
    for (int i = 0; i < 8; i++) sqa[i] = g_SQ[bz*1024 + arow0 + ty*8 + i];
    #pragma unroll
    for (int j = 0; j < 8; j++) sqb[j] = g_SQ[bz*1024 + brow0 + tx*8 + j];

    #pragma unroll
    for (int i = 0; i < 8; i++) {
        size_t base = (size_t)(bz*1024 + arow0 + ty*8 + i)*1024 + brow0 + tx*8;
        float4 o0, o1;
        o0.x = 2.f*acc[i][0]-sqb[0]; o0.y = 2.f*acc[i][1]-sqb[1];
        o0.z = 2.f*acc[i][2]-sqb[2]; o0.w = 2.f*acc[i][3]-sqb[3];
        o1.x = 2.f*acc[i][4]-sqb[4]; o1.y = 2.f*acc[i][5]-sqb[5];
        o1.z = 2.f*acc[i][6]-sqb[6]; o1.w = 2.f*acc[i][7]-sqb[7];
        *(float4*)&g_G[base]   = o0;
        *(float4*)&g_G[base+4] = o1;
    }

    if (ib != jb) {
        float (*tbuf)[132] = sAs;
        #pragma unroll
        for (int p = 0; p < 8; p++) {
            __syncthreads();
            #pragma unroll
            for (int i = 0; i < 8; i++)
                tbuf[tx][ty*8 + i] = 2.f*acc[i][p] - sqa[i];
            __syncthreads();
            int rowIdx = t >> 4;
            int seg    = t & 15;
            size_t base = (size_t)(bz*1024 + brow0 + rowIdx*8 + p)*1024 + arow0 + seg*8;
            float4 o0 = {tbuf[rowIdx][seg*8+0], tbuf[rowIdx][seg*8+1],
                         tbuf[rowIdx][seg*8+2], tbuf[rowIdx][seg*8+3]};
            float4 o1 = {tbuf[rowIdx][seg*8+4], tbuf[rowIdx][seg*8+5],
                         tbuf[rowIdx][seg*8+6], tbuf[rowIdx][seg*8+7]};
            *(float4*)&g_G[base]   = o0;
            *(float4*)&g_G[base+4] = o1;
        }
    }
}

// =======================================================================
// 128x128x16 SGEMM (NT), reg-prefetch pipelined.
// EPI 1: plain store to g_Z2. EPI 2: gemm5 fused stats.
// =======================================================================
template<int EPI>
__global__ void __launch_bounds__(256, 2)
sgemm128(const float* __restrict__ A, int lda,
         const float* __restrict__ B, int ldb,
         int K, int N2) {
    __shared__ __align__(16) float sAs[16][132];
    __shared__ __align__(16) float sBs[16][132];

    int t  = threadIdx.x;
    int tx = t & 15, ty = t >> 4;
    int arow0 = blockIdx.x*128;
    int n0    = blockIdx.y*128;

    const float* Abase = A + (size_t)arow0 * lda;
    const float* Bbase = B + (size_t)n0 * ldb;

    float acc[8][8];
    #pragma unroll
    for (int i = 0; i < 8; i++)
        #pragma unroll
        for (int j = 0; j < 8; j++) acc[i][j] = 0.f;

    int lrow[2], lq[2];
    #pragma unroll
    for (int rr = 0; rr < 2; rr++) { int f = t + rr*256; lrow[rr] = f >> 2; lq[rr] = f & 3; }

    float4 va[2], vb[2];
    #pragma unroll
    for (int rr = 0; rr < 2; rr++) {
        va[rr] = *(const float4*)(Abase + (size_t)lrow[rr]*lda + lq[rr]*4);
        vb[rr] = *(const float4*)(Bbase + (size_t)lrow[rr]*ldb + lq[rr]*4);
    }

    for (int kt = 0; kt < K; kt += 16) {
        #pragma unroll
        for (int rr = 0; rr < 2; rr++) {
            sAs[lq[rr]*4+0][lrow[rr]] = va[rr].x; sAs[lq[rr]*4+1][lrow[rr]] = va[rr].y;
            sAs[lq[rr]*4+2][lrow[rr]] = va[rr].z; sAs[lq[rr]*4+3][lrow[rr]] = va[rr].w;
            sBs[lq[rr]*4+0][lrow[rr]] = vb[rr].x; sBs[lq[rr]*4+1][lrow[rr]] = vb[rr].y;
            sBs[lq[rr]*4+2][lrow[rr]] = vb[rr].z; sBs[lq[rr]*4+3][lrow[rr]] = vb[rr].w;
        }
        __syncthreads();
        if (kt + 16 < K) {
            #pragma unroll
            for (int rr = 0; rr < 2; rr++) {
                va[rr] = *(const float4*)(Abase + (size_t)lrow[rr]*lda + kt + 16 + lq[rr]*4);
                vb[rr] = *(const float4*)(Bbase + (size_t)lrow[rr]*ldb + kt + 16 + lq[rr]*4);
            }
        }
        #pragma unroll
        for (int k = 0; k < 16; k++) {
            float4 a0 = *(const float4*)&sAs[k][ty*8];
            float4 a1 = *(const float4*)&sAs[k][ty*8 + 4];
            float4 b0 = *(const float4*)&sBs[k][tx*8];
            float4 b1 = *(const float4*)&sBs[k][tx*8 + 4];
            float av[8] = {a0.x, a0.y, a0.z, a0.w, a1.x, a1.y, a1.z, a1.w};
            float bv[8] = {b0.x, b0.y, b0.z, b0.w, b1.x, b1.y, b1.z, b1.w};
            #pragma unroll
            for (int i = 0; i < 8; i++)
                #pragma unroll
                for (int j = 0; j < 8; j++) acc[i][j] = fmaf(av[i], bv[j], acc[i][j]);
        }
        __syncthreads();
    }

    if (EPI == 1) {
        #pragma unroll
        for (int i = 0; i < 8; i++) {
            size_t base = (size_t)(arow0 + ty*8 + i)*N2 + n0 + tx*8;
            float4 o0 = {acc[i][0], acc[i][1], acc[i][2], acc[i][3]};
            float4 o1 = {acc[i][4], acc[i][5], acc[i][6], acc[i][7]};
            *(float4*)&g_Z2[base]   = o0;
            *(float4*)&g_Z2[base+4] = o1;
        }
    } else {
        double*   ssum = reinterpret_cast<double*>(&sAs[0][0]);
        double*   ssq  = ssum + 128;
        unsigned* smx  = reinterpret_cast<unsigned*>(ssq + 128);
        unsigned* smn  = smx + 128;
        if (t < 128) { ssum[t] = 0.0; ssq[t] = 0.0; smx[t] = 0u; smn[t] = 0xFFFFFFFFu; }
        __syncthreads();
        #pragma unroll
        for (int j = 0; j < 8; j++) {
            float s = 0.f, s2 = 0.f, mx = -FLT_MAX, mn = FLT_MAX;
            #pragma unroll
            for (int i = 0; i < 8; i++) {
                float y = acc[i][j];
                s += y; s2 = fmaf(y, y, s2);
                mx = fmaxf(mx, y); mn = fminf(mn, y);
            }
            int col = tx*8 + j;
            atomicAdd(&ssum[col], (double)s);
            atomicAdd(&ssq[col],  (double)s2);
            atomicMax(&smx[col], encf(mx));
            atomicMin(&smn[col], encf(mn));
        }
        __syncthreads();
        if (t < 128) {
            int o = n0 + t;
            int b = arow0 >> 10;
            atomicAdd(&g_SUM[o],   ssum[t]);
            atomicAdd(&g_SUMSQ[o], ssq[t]);
            atomicMax(&g_MXU[b*512 + o], smx[t]);
            atomicMin(&g_MNU[b*512 + o], smn[t]);
        }
    }
}

// ---------------- stage-1 zgemm (C=3) ----------------
template<int C, int N2>
__global__ void zgemm_kernel(const float* __restrict__ X, int ld, int off,
                             const float* __restrict__ W) {
    constexpr int TC = (C < 32) ? C : 32;
    __shared__ float As[64][TC+1];
    __shared__ float Bs[64][TC+1];
    int r0 = blockIdx.x * 64;
    int o0 = blockIdx.y * 64;
    int tx = threadIdx.x & 15, ty = threadIdx.x >> 4;
    float acc[4][4];
    #pragma unroll
    for (int i = 0; i < 4; i++)
        #pragma unroll
        for (int j = 0; j < 4; j++) acc[i][j] = 0.f;
    for (int c0 = 0; c0 < C; c0 += TC) {
        for (int i = threadIdx.x; i < 64*TC; i += 256) {
            int r = i / TC, c = i - r*TC;
            As[r][c] = X[(size_t)(r0 + r)*ld + off + c0 + c];
            Bs[r][c] = W[(size_t)(o0 + r)*C + c0 + c];
        }
        __syncthreads();
        for (int c = 0; c < TC; c++) {
            float av[4], bv[4];
            #pragma unroll
            for (int i = 0; i < 4; i++) { av[i] = As[ty*4+i][c]; bv[i] = Bs[tx*4+i][c]; }
            #pragma unroll
            for (int i = 0; i < 4; i++)
                #pragma unroll
                for (int j = 0; j < 4; j++) acc[i][j] = fmaf(av[i], bv[j], acc[i][j]);
        }
        __syncthreads();
    }
    #pragma unroll
    for (int i = 0; i < 4; i++)
        #pragma unroll
        for (int j = 0; j < 4; j++)
            g_Z2[(size_t)(r0 + ty*4 + i)*N2 + o0 + tx*4 + j] = acc[i][j];
}

// ---------------- warp top-20 pop via redux.sync ----------------
// Returns winner global index; caller pops if it owns it.
__device__ __forceinline__ unsigned topk_pop(float m1, int s1, int l) {
    unsigned key  = encf(m1);
    unsigned kmax = __reduce_max_sync(0xFFFFFFFFu, key);
    unsigned me   = (unsigned)((s1 << 5) | l);
    unsigned cand = (key == kmax) ? me : 0xFFFFFFFFu;
    return __reduce_min_sync(0xFFFFFFFFu, cand);
}

// ---------------- stage-1 fused distances + top-20 ----------------
__global__ void topk1_kernel(const float* __restrict__ x) {
    __shared__ float spx[1024], spy[1024], spz[1024], ssq[1024];
    int n0 = blockIdx.x * 8;
    int b  = n0 >> 10;
    int t  = threadIdx.x;
    const float* xb = x + (size_t)b * 3072;
    for (int m = t; m < 1024; m += 256) {
        float px = xb[m*3], py = xb[m*3+1], pz = xb[m*3+2];
        spx[m] = px; spy[m] = py; spz[m] = pz;
        ssq[m] = fmaf(px, px, fmaf(py, py, pz*pz));
    }
    __syncthreads();

    int warp = t >> 5, l = t & 31;
    int ln = (n0 & 1023) + warp;
    float dnx = 2.f*spx[ln], dny = 2.f*spy[ln], dnz = 2.f*spz[ln];

    float v[32];
    #pragma unroll
    for (int s = 0; s < 32; s++) {
        int m = s*32 + l;
        v[s] = fmaf(dnx, spx[m], fmaf(dny, spy[m], fmaf(dnz, spz[m], -ssq[m])));
    }

    float m1 = -FLT_MAX, m2 = -FLT_MAX;
    int s1 = 0, s2 = 0;
    #pragma unroll
    for (int s = 0; s < 32; s++) {
        float xv = v[s];
        if (xv > m2) {
            if (xv > m1) { m2 = m1; s2 = s1; m1 = xv; s1 = s; }
            else         { m2 = xv; s2 = s; }
        }
    }
    bool dirty = false;
    int row = n0 + warp;
    for (int j = 0; j < KNN; j++) {
        unsigned win = topk_pop(m1, s1, l);
        if (l == 0) g_IDX[row*KNN + j] = (int)win;
        if (win == (unsigned)((s1 << 5) | l)) {
            #pragma unroll
            for (int s = 0; s < 32; s++) if (s == s1) v[s] = -FLT_MAX;
            if (!dirty) { m1 = m2; s1 = s2; dirty = true; }
            else {
                m1 = -FLT_MAX; m2 = -FLT_MAX; s1 = 0; s2 = 0;
                #pragma unroll
                for (int s = 0; s < 32; s++) {
                    float xv = v[s];
                    if (xv > m2) {
                        if (xv > m1) { m2 = m1; s2 = s1; m1 = xv; s1 = s; }
                        else         { m2 = xv; s2 = s; }
                    }
                }
                dirty = false;
            }
        }
    }
}

// ---------------- top-20 from g_G (stages 2-4) ----------------
__global__ void topk_kernel() {
    int warp = (blockIdx.x << 3) + (threadIdx.x >> 5);
    int l = threadIdx.x & 31;
    const float* grow = g_G + (size_t)warp * NN;
    float v[32];
    #pragma unroll
    for (int s = 0; s < 32; s++) v[s] = grow[s*32 + l];

    float m1 = -FLT_MAX, m2 = -FLT_MAX;
    int s1 = 0, s2 = 0;
    #pragma unroll
    for (int s = 0; s < 32; s++) {
        float x = v[s];
        if (x > m2) {
            if (x > m1) { m2 = m1; s2 = s1; m1 = x; s1 = s; }
            else        { m2 = x;  s2 = s; }
        }
    }
    bool dirty = false;

    for (int j = 0; j < KNN; j++) {
        unsigned win = topk_pop(m1, s1, l);
        if (l == 0) g_IDX[warp*KNN + j] = (int)win;
        if (win == (unsigned)((s1 << 5) | l)) {
            #pragma unroll
            for (int s = 0; s < 32; s++) if (s == s1) v[s] = -FLT_MAX;
            if (!dirty) { m1 = m2; s1 = s2; dirty = true; }
            else {
                m1 = -FLT_MAX; m2 = -FLT_MAX; s1 = 0; s2 = 0;
                #pragma unroll
                for (int s = 0; s < 32; s++) {
                    float x = v[s];
                    if (x > m2) {
                        if (x > m1) { m2 = m1; s2 = s1; m1 = x; s1 = s; }
                        else        { m2 = x;  s2 = s; }
                    }
                }
                dirty = false;
            }
        }
    }
}

// ---------------- gather + k-reduce: float4 per thread, smem stats ----------------
template<int O>
__global__ void gather_kernel() {
    constexpr int TP  = O / 4;
    constexpr int PPB = 256 / TP;
    __shared__ int   sidx[PPB*KNN];
    __shared__ float ssum[O], ssq2[O];

    int n0 = blockIdx.x * PPB;
    int b  = n0 >> 10;
    int t  = threadIdx.x;
    if (t < O) { ssum[t] = 0.f; ssq2[t] = 0.f; }
    for (int i = t; i < PPB*KNN; i += 256) sidx[i] = g_IDX[n0*KNN + i];
    __syncthreads();

    int p  = t / TP;
    int cg = (t % TP) * 4;
    int n  = n0 + p;
    const float* Zb = g_Z2 + ((size_t)b << 10) * (2*O);

    float4 ctr = *(const float4*)&g_Z2[(size_t)n*(2*O) + O + cg];
    float4 mx = {-FLT_MAX, -FLT_MAX, -FLT_MAX, -FLT_MAX};
    float4 mn = { FLT_MAX,  FLT_MAX,  FLT_MAX,  FLT_MAX};
    float4 s  = {0.f, 0.f, 0.f, 0.f};
    float4 s2 = {0.f, 0.f, 0.f, 0.f};

    #pragma unroll
    for (int j = 0; j < KNN; j++) {
        int m = sidx[p*KNN + j];
        float4 z = *(const float4*)&Zb[(size_t)m*(2*O) + cg];
        mx.x = fmaxf(mx.x, z.x); mn.x = fminf(mn.x, z.x); s.x += z.x; s2.x = fmaf(z.x, z.x, s2.x);
        mx.y = fmaxf(mx.y, z.y); mn.y = fminf(mn.y, z.y); s.y += z.y; s2.y = fmaf(z.y, z.y, s2.y);
        mx.z = fmaxf(mx.z, z.z); mn.z = fminf(mn.z, z.z); s.z += z.z; s2.z = fmaf(z.z, z.z, s2.z);
        mx.w = fmaxf(mx.w, z.w); mn.w = fminf(mn.w, z.w); s.w += z.w; s2.w = fmaf(z.w, z.w, s2.w);
    }

    float4 omx = {mx.x + ctr.x, mx.y + ctr.y, mx.z + ctr.z, mx.w + ctr.w};
    float4 omn = {mn.x + ctr.x, mn.y + ctr.y, mn.z + ctr.z, mn.w + ctr.w};
    *(float4*)&g_YMAX[(size_t)n*O + cg] = omx;
    *(float4*)&g_YMIN[(size_t)n*O + cg] = omn;

    const float KF = (float)KNN;
    atomicAdd(&ssum[cg+0], s.x + KF*ctr.x);
    atomicAdd(&ssum[cg+1], s.y + KF*ctr.y);
    atomicAdd(&ssum[cg+2], s.z + KF*ctr.z);
    atomicAdd(&ssum[cg+3], s.w + KF*ctr.w);
    atomicAdd(&ssq2[cg+0], s2.x + 2.f*ctr.x*s.x + KF*ctr.x*ctr.x);
    atomicAdd(&ssq2[cg+1], s2.y + 2.f*ctr.y*s.y + KF*ctr.y*ctr.y);
    atomicAdd(&ssq2[cg+2], s2.z + 2.f*ctr.z*s.z + KF*ctr.z*ctr.z);
    atomicAdd(&ssq2[cg+3], s2.w + 2.f*ctr.w*s.w + KF*ctr.w*ctr.w);
    __syncthreads();
    if (t < O) {
        atomicAdd(&g_SUM[t],   (double)ssum[t]);
        atomicAdd(&g_SUMSQ[t], (double)ssq2[t]);
    }
}

// ---------------- BN affine coeffs; self-resets accumulators ----------------
__global__ void stats_kernel(const float* __restrict__ g, const float* __restrict__ beta,
                             float count, int O, int resetMM) {
    int o = threadIdx.x;
    if (resetMM) {
        for (int i = o; i < BB*512; i += 512) { g_MXU[i] = 0u; g_MNU[i] = 0xFFFFFFFFu; }
    }
    if (o >= O) return;
    double m   = g_SUM[o]   / (double)count;
    double var = g_SUMSQ[o] / (double)count - m*m;
    float a = g[o] / sqrtf((float)var + 1e-5f);
    g_A[o]  = a;
    g_Cc[o] = beta[o] - (float)m * a;
    g_SUM[o] = 0.0; g_SUMSQ[o] = 0.0;
}

__global__ void apply_kernel(int O, int outOff) {
    int i = blockIdx.x * blockDim.x + threadIdx.x;
    if (i >= BB*NN*O) return;
    int o  = i % O;
    int bn = i / O;
    float a = g_A[o], c = g_Cc[o];
    float sel = (a >= 0.f) ? g_YMAX[i] : g_YMIN[i];
    float v = fmaf(a, sel, c);
    g_FEAT[(size_t)bn*512 + outOff + o] = (v >= 0.f) ? v : 0.2f*v;
}

// ---------------- final norm + global max + embedding ----------------
__global__ void emb_kernel(const float* __restrict__ wemb, float* __restrict__ out) {
    __shared__ float feat[512];
    int b = blockIdx.x, t = threadIdx.x;
    for (int o = t; o < 512; o += 256) {
        float a = g_A[o], c = g_Cc[o];
        float sel = (a >= 0.f) ? decf(g_MXU[b*512 + o]) : decf(g_MNU[b*512 + o]);
        float v = fmaf(a, sel, c);
        feat[o] = (v >= 0.f) ? v : 0.2f*v;
    }
    __syncthreads();
    const float* wr = wemb + (size_t)t * 512;
    float s = 0.f;
    for (int c = 0; c < 512; c++) s = fmaf(wr[c], feat[c], s);
    out[b*256 + t] = s;
}

// ---------------- host orchestration ----------------
template<int C, int O>
static void run_edge_big(const float* feat, int off, const float* wcat,
                         const float* g, const float* beta, int outOff, int resetMM) {
    sq_kernel<C><<<32, 256>>>(feat, 512, off);
    dim3 gg(36, 1, BB);
    gram_sym<<<gg, 256>>>(feat + off, 512, C);
    topk_kernel<<<BB*NN/8, 256>>>();
    dim3 zg(64, (2*O)/128, 1);
    sgemm128<1><<<zg, 256>>>(feat + off, 512, wcat, C, C, 2*O);
    gather_kernel<O><<<BB*NN/(256/(O/4)), 256>>>();
    stats_kernel<<<1, 512>>>(g, beta, (float)(BB*NN*KNN), O, resetMM);
    apply_kernel<<<(BB*NN*O + 255)/256, 256>>>(O, outOff);
}

extern "C" void kernel_launch(void* const* d_in, const int* in_sizes, int n_in,
                              void* d_out, int out_size) {
    (void)in_sizes; (void)n_in; (void)out_size;
    const float* x    = (const float*)d_in[0];
    const float* w1   = (const float*)d_in[1];
    const float* g1   = (const float*)d_in[2];
    const float* b1   = (const float*)d_in[3];
    const float* w2   = (const float*)d_in[4];
    const float* g2   = (const float*)d_in[5];
    const float* b2   = (const float*)d_in[6];
    const float* w3   = (const float*)d_in[7];
    const float* g3   = (const float*)d_in[8];
    const float* b3   = (const float*)d_in[9];
    const float* w4   = (const float*)d_in[10];
    const float* g4   = (const float*)d_in[11];
    const float* b4   = (const float*)d_in[12];
    const float* w5   = (const float*)d_in[13];
    const float* g5   = (const float*)d_in[14];
    const float* b5   = (const float*)d_in[15];
    const float* wemb = (const float*)d_in[16];
    float* out = (float*)d_out;

    float *feat, *wcat;
    cudaGetSymbolAddress((void**)&feat, g_FEAT);
    cudaGetSymbolAddress((void**)&wcat, g_WCAT);

    prep_kernel<<<(90496 + 255)/256, 256>>>(w1, w2, w3, w4);

    // ---- stage 1 (C=3): fused distance + topk, small zgemm ----
    topk1_kernel<<<BB*NN/8, 256>>>(x);
    dim3 zg1(BB*NN/64, 2);
    zgemm_kernel<3, 128><<<zg1, 256>>>(x, 3, 0, wcat);
    gather_kernel<64><<<BB*NN/16, 256>>>();
    stats_kernel<<<1, 512>>>(g1, b1, (float)(BB*NN*KNN), 64, 0);
    apply_kernel<<<(BB*NN*64 + 255)/256, 256>>>(64, 0);

    // ---- stages 2-4: symmetric gram + SGEMM path ----
    run_edge_big<64,  64 >(feat, 0,   wcat + 384,   g2, b2, 64, 0);
    run_edge_big<64,  128>(feat, 64,  wcat + 8576,  g3, b3, 128, 0);
    run_edge_big<128, 256>(feat, 128, wcat + 24960, g4, b4, 256, 1);

    // ---- final conv 512x512 fused with stats + max/min ----
    dim3 g5g(64, 4, 1);
    sgemm128<2><<<g5g, 256>>>(feat, 512, w5, 512, 512, 0);
    stats_kernel<<<1, 512>>>(g5, b5, (float)(BB*NN), 512, 0);
    emb_kernel<<<BB, 256>>>(wemb, out);
}

// round 8
// speedup vs baseline: 1.6744x; 1.0445x over previous
#include <cuda_runtime.h>
#include <math.h>
#include <float.h>

#define BB 8
#define NN 1024
#define KNN 20

// ---------------- static device scratch ----------------
__device__ float    g_G[(size_t)BB*NN*NN];        // pairwise 2*dot - sq[m]
__device__ float    g_SQ[BB*NN];
__device__ int      g_IDX[BB*NN*KNN];
__device__ float    g_Z2[(size_t)BB*NN*512];      // [bn][2O]: Zn | Zc
__device__ float    g_FEAT[(size_t)BB*NN*512];    // concat features (bn, c)
__device__ float    g_YMAX[(size_t)BB*NN*256];
__device__ float    g_YMIN[(size_t)BB*NN*256];
__device__ double   g_SUM[512];
__device__ double   g_SUMSQ[512];
__device__ float    g_A[512];
__device__ float    g_Cc[512];
__device__ float    g_WCAT[90496];                // [Wn ; Wc-Wn] per block
__device__ unsigned g_MXU[BB*512];
__device__ unsigned g_MNU[BB*512];

__device__ __forceinline__ unsigned encf(float f) {
    unsigned b = __float_as_uint(f);
    return (b & 0x80000000u) ? ~b : (b | 0x80000000u);
}
__device__ __forceinline__ float decf(unsigned u) {
    return __uint_as_float((u & 0x80000000u) ? (u & 0x7FFFFFFFu) : ~u);
}

// WCAT offsets: b1:0 (128x3), b2:384 (128x64), b3:8576 (256x64), b4:24960 (512x128)
__global__ void prep_kernel(const float* __restrict__ w1, const float* __restrict__ w2,
                            const float* __restrict__ w3, const float* __restrict__ w4) {
    int t = blockIdx.x * blockDim.x + threadIdx.x;
    if (t < 384) {
        int r = t/3, c = t%3;
        g_WCAT[t] = (r < 64) ? w1[r*6 + c] : (w1[(r-64)*6 + 3 + c] - w1[(r-64)*6 + c]);
        return;
    }
    int u = t - 384;
    if (u < 8192) {
        int r = u/64, c = u%64;
        g_WCAT[384 + u] = (r < 64) ? w2[r*128 + c] : (w2[(r-64)*128 + 64 + c] - w2[(r-64)*128 + c]);
        return;
    }
    u -= 8192;
    if (u < 16384) {
        int r = u/64, c = u%64;
        g_WCAT[8576 + u] = (r < 128) ? w3[r*128 + c] : (w3[(r-128)*128 + 64 + c] - w3[(r-128)*128 + c]);
        return;
    }
    u -= 16384;
    if (u < 65536) {
        int r = u/128, c = u%128;
        g_WCAT[24960 + u] = (r < 256) ? w4[r*256 + c] : (w4[(r-256)*256 + 128 + c] - w4[(r-256)*256 + c]);
        return;
    }
}

// =======================================================================
// Symmetric gram, double-buffered: block per (i<=j) 128x128 tile pair.
// =======================================================================
__global__ void __launch_bounds__(256, 2)
gram_sym(const float* __restrict__ A, int lda, int K) {
    __shared__ __align__(16) float sA[2][16][132];
    __shared__ __align__(16) float sB[2][16][132];

    int t  = threadIdx.x;
    int tx = t & 15, ty = t >> 4;
    int bz = blockIdx.z;

    int idx = blockIdx.x;
    int ib = 0;
    while (idx >= 8 - ib) { idx -= 8 - ib; ib++; }
    int jb = ib + idx;

    int arow0 = ib * 128;
    int brow0 = jb * 128;
    const float* Abase = A + (size_t)(bz*1024 + arow0) * lda;
    const float* Bbase = A + (size_t)(bz*1024 + brow0) * lda;

    float acc[8][8];
    #pragma unroll
    for (int i = 0; i < 8; i++)
        #pragma unroll
        for (int j = 0; j < 8; j++) acc[i][j] = 0.f;

    int lrow[2], lq[2];
    #pragma unroll
    for (int rr = 0; rr < 2; rr++) { int f = t + rr*256; lrow[rr] = f >> 2; lq[rr] = f & 3; }

    float4 va[2], vb[2];
    #pragma unroll
    for (int rr = 0; rr < 2; rr++) {
        va[rr] = *(const float4*)(Abase + (size_t)lrow[rr]*lda + lq[rr]*4);
        vb[rr] = *(const float4*)(Bbase + (size_t)lrow[rr]*lda + lq[rr]*4);
    }
    #pragma unroll
    for (int rr = 0; rr < 2; rr++) {
        sA[0][lq[rr]*4+0][lrow[rr]] = va[rr].x; sA[0][lq[rr]*4+1][lrow[rr]] = va[rr].y;
        sA[0][lq[rr]*4+2][lrow[rr]] = va[rr].z; sA[0][lq[rr]*4+3][lrow[rr]] = va[rr].w;
        sB[0][lq[rr]*4+0][lrow[rr]] = vb[rr].x; sB[0][lq[rr]*4+1][lrow[rr]] = vb[rr].y;
        sB[0][lq[rr]*4+2][lrow[rr]] = vb[rr].z; sB[0][lq[rr]*4+3][lrow[rr]] = vb[rr].w;
    }
    __syncthreads();

    int KT = K >> 4;
    int buf = 0;
    for (int kt = 0; kt < KT; kt++) {
        bool hasNext = (kt + 1 < KT);
        if (hasNext) {
            int koff = (kt + 1) * 16;
            #pragma unroll
            for (int rr = 0; rr < 2; rr++) {
                va[rr] = *(const float4*)(Abase + (size_t)lrow[rr]*lda + koff + lq[rr]*4);
                vb[rr] = *(const float4*)(Bbase + (size_t)lrow[rr]*lda + koff + lq[rr]*4);
            }
        }
        #pragma unroll
        for (int k = 0; k < 16; k++) {
            float4 a0 = *(const float4*)&sA[buf][k][ty*8];
            float4 a1 = *(const float4*)&sA[buf][k][ty*8 + 4];
            float4 b0 = *(const float4*)&sB[buf][k][tx*8];
            float4 b1 = *(const float4*)&sB[buf][k][tx*8 + 4];
            float av[8] = {a0.x, a0.y, a0.z, a0.w, a1.x, a1.y, a1.z, a1.w};
            float bv[8] = {b0.x, b0.y, b0.z, b0.w, b1.x, b1.y, b1.z, b1.w};
            #pragma unroll
            for (int i = 0; i < 8; i++)
                #pragma unroll
                for (int j = 0; j < 8; j++) acc[i][j] = fmaf(av[i], bv[j], acc[i][j]);
        }
        if (hasNext) {
            int nb = buf ^ 1;
            #pragma unroll
            for (int rr = 0; rr < 2; rr++) {
                sA[nb][lq[rr]*4+0][lrow[rr]] = va[rr].x; sA[nb][lq[rr]*4+1][lrow[rr]] = va[rr].y;
                sA[nb][lq[rr]*4+2][lrow[rr]] = va[rr].z; sA[nb][lq[rr]*4+3][lrow[rr]] = va[rr].w;
                sB[nb][lq[rr]*4+0][lrow[rr]] = vb[rr].x; sB[nb][lq[rr]*4+1][lrow[rr]] = vb[rr].y;
                sB[nb][lq[rr]*4+2][lrow[rr]] = vb[rr].z; sB[nb][lq[rr]*4+3][lrow[rr]] = vb[rr].w;
            }
            __syncthreads();
            buf = nb;
        }
    }
    __syncthreads();   // epilogue reuses smem

    float sqa[8], sqb[8];
    #pragma unroll
    for (int i = 0; i < 8; i++) sqa[i] = g_SQ[bz*1024 + arow0 + ty*8 + i];
    #pragma unroll
    for (int j = 0; j < 8; j++) sqb[j] = g_SQ[bz*1024 + brow0 + tx*8 + j];

    #pragma unroll
    for (int i = 0; i < 8; i++) {
        size_t base = (size_t)(bz*1024 + arow0 + ty*8 + i)*1024 + brow0 + tx*8;
        float4 o0, o1;
        o0.x = 2.f*acc[i][0]-sqb[0]; o0.y = 2.f*acc[i][1]-sqb[1];
        o0.z = 2.f*acc[i][2]-sqb[2]; o0.w = 2.f*acc[i][3]-sqb[3];
        o1.x = 2.f*acc[i][4]-sqb[4]; o1.y = 2.f*acc[i][5]-sqb[5];
        o1.z = 2.f*acc[i][6]-sqb[6]; o1.w = 2.f*acc[i][7]-sqb[7];
        *(float4*)&g_G[base]   = o0;
        *(float4*)&g_G[base+4] = o1;
    }

    if (ib != jb) {
        float (*tA)[132] = sA[0];
        float (*tB)[132] = sB[0];
        #pragma unroll
        for (int p = 0; p < 8; p += 2) {
            __syncthreads();
            #pragma unroll
            for (int i = 0; i < 8; i++) {
                tA[tx][ty*8 + i] = 2.f*acc[i][p]   - sqa[i];
                tB[tx][ty*8 + i] = 2.f*acc[i][p+1] - sqa[i];
            }
            __syncthreads();
            int rowIdx = t >> 4;
            int seg    = t & 15;
            size_t b0 = (size_t)(bz*1024 + brow0 + rowIdx*8 + p)*1024 + arow0 + seg*8;
            size_t b1 = (size_t)(bz*1024 + brow0 + rowIdx*8 + p + 1)*1024 + arow0 + seg*8;
            float4 u0 = {tA[rowIdx][seg*8+0], tA[rowIdx][seg*8+1],
                         tA[rowIdx][seg*8+2], tA[rowIdx][seg*8+3]};
            float4 u1 = {tA[rowIdx][seg*8+4], tA[rowIdx][seg*8+5],
                         tA[rowIdx][seg*8+6], tA[rowIdx][seg*8+7]};
            float4 w0 = {tB[rowIdx][seg*8+0], tB[rowIdx][seg*8+1],
                         tB[rowIdx][seg*8+2], tB[rowIdx][seg*8+3]};
            float4 w1 = {tB[rowIdx][seg*8+4], tB[rowIdx][seg*8+5],
                         tB[rowIdx][seg*8+6], tB[rowIdx][seg*8+7]};
            *(float4*)&g_G[b0]   = u0;
            *(float4*)&g_G[b0+4] = u1;
            *(float4*)&g_G[b1]   = w0;
            *(float4*)&g_G[b1+4] = w1;
        }
    }
}

// =======================================================================
// 128x128x16 SGEMM (NT), double-buffered.
// EPI 1: plain store to g_Z2. EPI 2: gemm5 fused stats.
// =======================================================================
template<int EPI>
__global__ void __launch_bounds__(256, 2)
sgemm128(const float* __restrict__ A, int lda,
         const float* __restrict__ B, int ldb,
         int K, int N2) {
    __shared__ __align__(16) float sA[2][16][132];
    __shared__ __align__(16) float sB[2][16][132];

    int t  = threadIdx.x;
    int tx = t & 15, ty = t >> 4;
    int arow0 = blockIdx.x*128;
    int n0    = blockIdx.y*128;

    const float* Abase = A + (size_t)arow0 * lda;
    const float* Bbase = B + (size_t)n0 * ldb;

    float acc[8][8];
    #pragma unroll
    for (int i = 0; i < 8; i++)
        #pragma unroll
        for (int j = 0; j < 8; j++) acc[i][j] = 0.f;

    int lrow[2], lq[2];
    #pragma unroll
    for (int rr = 0; rr < 2; rr++) { int f = t + rr*256; lrow[rr] = f >> 2; lq[rr] = f & 3; }

    float4 va[2], vb[2];
    #pragma unroll
    for (int rr = 0; rr < 2; rr++) {
        va[rr] = *(const float4*)(Abase + (size_t)lrow[rr]*lda + lq[rr]*4);
        vb[rr] = *(const float4*)(Bbase + (size_t)lrow[rr]*ldb + lq[rr]*4);
    }
    #pragma unroll
    for (int rr = 0; rr < 2; rr++) {
        sA[0][lq[rr]*4+0][lrow[rr]] = va[rr].x; sA[0][lq[rr]*4+1][lrow[rr]] = va[rr].y;
        sA[0][lq[rr]*4+2][lrow[rr]] = va[rr].z; sA[0][lq[rr]*4+3][lrow[rr]] = va[rr].w;
        sB[0][lq[rr]*4+0][lrow[rr]] = vb[rr].x; sB[0][lq[rr]*4+1][lrow[rr]] = vb[rr].y;
        sB[0][lq[rr]*4+2][lrow[rr]] = vb[rr].z; sB[0][lq[rr]*4+3][lrow[rr]] = vb[rr].w;
    }
    __syncthreads();

    int KT = K >> 4;
    int buf = 0;
    for (int kt = 0; kt < KT; kt++) {
        bool hasNext = (kt + 1 < KT);
        if (hasNext) {
            int koff = (kt + 1) * 16;
            #pragma unroll
            for (int rr = 0; rr < 2; rr++) {
                va[rr] = *(const float4*)(Abase + (size_t)lrow[rr]*lda + koff + lq[rr]*4);
                vb[rr] = *(const float4*)(Bbase + (size_t)lrow[rr]*ldb + koff + lq[rr]*4);
            }
        }
        #pragma unroll
        for (int k = 0; k < 16; k++) {
            float4 a0 = *(const float4*)&sA[buf][k][ty*8];
            float4 a1 = *(const float4*)&sA[buf][k][ty*8 + 4];
            float4 b0 = *(const float4*)&sB[buf][k][tx*8];
            float4 b1 = *(const float4*)&sB[buf][k][tx*8 + 4];
            float av[8] = {a0.x, a0.y, a0.z, a0.w, a1.x, a1.y, a1.z, a1.w};
            float bv[8] = {b0.x, b0.y, b0.z, b0.w, b1.x, b1.y, b1.z, b1.w};
            #pragma unroll
            for (int i = 0; i < 8; i++)
                #pragma unroll
                for (int j = 0; j < 8; j++) acc[i][j] = fmaf(av[i], bv[j], acc[i][j]);
        }
        if (hasNext) {
            int nb = buf ^ 1;
            #pragma unroll
            for (int rr = 0; rr < 2; rr++) {
                sA[nb][lq[rr]*4+0][lrow[rr]] = va[rr].x; sA[nb][lq[rr]*4+1][lrow[rr]] = va[rr].y;
                sA[nb][lq[rr]*4+2][lrow[rr]] = va[rr].z; sA[nb][lq[rr]*4+3][lrow[rr]] = va[rr].w;
                sB[nb][lq[rr]*4+0][lrow[rr]] = vb[rr].x; sB[nb][lq[rr]*4+1][lrow[rr]] = vb[rr].y;
                sB[nb][lq[rr]*4+2][lrow[rr]] = vb[rr].z; sB[nb][lq[rr]*4+3][lrow[rr]] = vb[rr].w;
            }
            __syncthreads();
            buf = nb;
        }
    }
    __syncthreads();   // epilogue may reuse smem

    if (EPI == 1) {
        #pragma unroll
        for (int i = 0; i < 8; i++) {
            size_t base = (size_t)(arow0 + ty*8 + i)*N2 + n0 + tx*8;
            float4 o0 = {acc[i][0], acc[i][1], acc[i][2], acc[i][3]};
            float4 o1 = {acc[i][4], acc[i][5], acc[i][6], acc[i][7]};
            *(float4*)&g_Z2[base]   = o0;
            *(float4*)&g_Z2[base+4] = o1;
        }
    } else {
        double*   ssum = reinterpret_cast<double*>(&sA[0][0][0]);
        double*   ssq  = ssum + 128;
        unsigned* smx  = reinterpret_cast<unsigned*>(ssq + 128);
        unsigned* smn  = smx + 128;
        if (t < 128) { ssum[t] = 0.0; ssq[t] = 0.0; smx[t] = 0u; smn[t] = 0xFFFFFFFFu; }
        __syncthreads();
        #pragma unroll
        for (int j = 0; j < 8; j++) {
            float s = 0.f, s2 = 0.f, mx = -FLT_MAX, mn = FLT_MAX;
            #pragma unroll
            for (int i = 0; i < 8; i++) {
                float y = acc[i][j];
                s += y; s2 = fmaf(y, y, s2);
                mx = fmaxf(mx, y); mn = fminf(mn, y);
            }
            int col = tx*8 + j;
            atomicAdd(&ssum[col], (double)s);
            atomicAdd(&ssq[col],  (double)s2);
            atomicMax(&smx[col], encf(mx));
            atomicMin(&smn[col], encf(mn));
        }
        __syncthreads();
        if (t < 128) {
            int o = n0 + t;
            int b = arow0 >> 10;
            atomicAdd(&g_SUM[o],   ssum[t]);
            atomicAdd(&g_SUMSQ[o], ssq[t]);
            atomicMax(&g_MXU[b*512 + o], smx[t]);
            atomicMin(&g_MNU[b*512 + o], smn[t]);
        }
    }
}

// ---------------- stage-1 zgemm (C=3) ----------------
template<int C, int N2>
__global__ void zgemm_kernel(const float* __restrict__ X, int ld, int off,
                             const float* __restrict__ W) {
    constexpr int TC = (C < 32) ? C : 32;
    __shared__ float As[64][TC+1];
    __shared__ float Bs[64][TC+1];
    int r0 = blockIdx.x * 64;
    int o0 = blockIdx.y * 64;
    int tx = threadIdx.x & 15, ty = threadIdx.x >> 4;
    float acc[4][4];
    #pragma unroll
    for (int i = 0; i < 4; i++)
        #pragma unroll
        for (int j = 0; j < 4; j++) acc[i][j] = 0.f;
    for (int c0 = 0; c0 < C; c0 += TC) {
        for (int i = threadIdx.x; i < 64*TC; i += 256) {
            int r = i / TC, c = i - r*TC;
            As[r][c] = X[(size_t)(r0 + r)*ld + off + c0 + c];
            Bs[r][c] = W[(size_t)(o0 + r)*C + c0 + c];
        }
        __syncthreads();
        for (int c = 0; c < TC; c++) {
            float av[4], bv[4];
            #pragma unroll
            for (int i = 0; i < 4; i++) { av[i] = As[ty*4+i][c]; bv[i] = Bs[tx*4+i][c]; }
            #pragma unroll
            for (int i = 0; i < 4; i++)
                #pragma unroll
                for (int j = 0; j < 4; j++) acc[i][j] = fmaf(av[i], bv[j], acc[i][j]);
        }
        __syncthreads();
    }
    #pragma unroll
    for (int i = 0; i < 4; i++)
        #pragma unroll
        for (int j = 0; j < 4; j++)
            g_Z2[(size_t)(r0 + ty*4 + i)*N2 + o0 + tx*4 + j] = acc[i][j];
}

// ---------------- warp top-20 pop via redux.sync ----------------
__device__ __forceinline__ unsigned topk_pop(float m1, int s1, int l) {
    unsigned key  = encf(m1);
    unsigned kmax = __reduce_max_sync(0xFFFFFFFFu, key);
    unsigned me   = (unsigned)((s1 << 5) | l);
    unsigned cand = (key == kmax) ? me : 0xFFFFFFFFu;
    return __reduce_min_sync(0xFFFFFFFFu, cand);
}

// ---------------- stage-1 fused distances + top-20 ----------------
__global__ void topk1_kernel(const float* __restrict__ x) {
    __shared__ float spx[1024], spy[1024], spz[1024], ssq[1024];
    int n0 = blockIdx.x * 8;
    int b  = n0 >> 10;
    int t  = threadIdx.x;
    const float* xb = x + (size_t)b * 3072;
    for (int m = t; m < 1024; m += 256) {
        float px = xb[m*3], py = xb[m*3+1], pz = xb[m*3+2];
        spx[m] = px; spy[m] = py; spz[m] = pz;
        ssq[m] = fmaf(px, px, fmaf(py, py, pz*pz));
    }
    __syncthreads();

    int warp = t >> 5, l = t & 31;
    int ln = (n0 & 1023) + warp;
    float dnx = 2.f*spx[ln], dny = 2.f*spy[ln], dnz = 2.f*spz[ln];

    float v[32];
    #pragma unroll
    for (int s = 0; s < 32; s++) {
        int m = s*32 + l;
        v[s] = fmaf(dnx, spx[m], fmaf(dny, spy[m], fmaf(dnz, spz[m], -ssq[m])));
    }

    float m1 = -FLT_MAX, m2 = -FLT_MAX;
    int s1 = 0, s2 = 0;
    #pragma unroll
    for (int s = 0; s < 32; s++) {
        float xv = v[s];
        if (xv > m2) {
            if (xv > m1) { m2 = m1; s2 = s1; m1 = xv; s1 = s; }
            else         { m2 = xv; s2 = s; }
        }
    }
    bool dirty = false;
    int row = n0 + warp;
    for (int j = 0; j < KNN; j++) {
        unsigned win = topk_pop(m1, s1, l);
        if (l == 0) g_IDX[row*KNN + j] = (int)win;
        if (win == (unsigned)((s1 << 5) | l)) {
            #pragma unroll
            for (int s = 0; s < 32; s++) if (s == s1) v[s] = -FLT_MAX;
            if (!dirty) { m1 = m2; s1 = s2; dirty = true; }
            else {
                m1 = -FLT_MAX; m2 = -FLT_MAX; s1 = 0; s2 = 0;
                #pragma unroll
                for (int s = 0; s < 32; s++) {
                    float xv = v[s];
                    if (xv > m2) {
                        if (xv > m1) { m2 = m1; s2 = s1; m1 = xv; s1 = s; }
                        else         { m2 = xv; s2 = s; }
                    }
                }
                dirty = false;
            }
        }
    }
}

// ---------------- top-20 from g_G (stages 2-4) ----------------
__global__ void topk_kernel() {
    int warp = (blockIdx.x << 3) + (threadIdx.x >> 5);
    int l = threadIdx.x & 31;
    const float* grow = g_G + (size_t)warp * NN;
    float v[32];
    #pragma unroll
    for (int s = 0; s < 32; s++) v[s] = grow[s*32 + l];

    float m1 = -FLT_MAX, m2 = -FLT_MAX;
    int s1 = 0, s2 = 0;
    #pragma unroll
    for (int s = 0; s < 32; s++) {
        float x = v[s];
        if (x > m2) {
            if (x > m1) { m2 = m1; s2 = s1; m1 = x; s1 = s; }
            else        { m2 = x;  s2 = s; }
        }
    }
    bool dirty = false;

    for (int j = 0; j < KNN; j++) {
        unsigned win = topk_pop(m1, s1, l);
        if (l == 0) g_IDX[warp*KNN + j] = (int)win;
        if (win == (unsigned)((s1 << 5) | l)) {
            #pragma unroll
            for (int s = 0; s < 32; s++) if (s == s1) v[s] = -FLT_MAX;
            if (!dirty) { m1 = m2; s1 = s2; dirty = true; }
            else {
                m1 = -FLT_MAX; m2 = -FLT_MAX; s1 = 0; s2 = 0;
                #pragma unroll
                for (int s = 0; s < 32; s++) {
                    float x = v[s];
                    if (x > m2) {
                        if (x > m1) { m2 = m1; s2 = s1; m1 = x; s1 = s; }
                        else        { m2 = x;  s2 = s; }
                    }
                }
                dirty = false;
            }
        }
    }
}

// ---------------- gather + k-reduce: float4 per thread, smem stats ----------------
template<int O>
__global__ void gather_kernel() {
    constexpr int TP  = O / 4;
    constexpr int PPB = 256 / TP;
    __shared__ int   sidx[PPB*KNN];
    __shared__ float ssum[O], ssq2[O];

    int n0 = blockIdx.x * PPB;
    int b  = n0 >> 10;
    int t  = threadIdx.x;
    if (t < O) { ssum[t] = 0.f; ssq2[t] = 0.f; }
    for (int i = t; i < PPB*KNN; i += 256) sidx[i] = g_IDX[n0*KNN + i];
    __syncthreads();

    int p  = t / TP;
    int cg = (t % TP) * 4;
    int n  = n0 + p;
    const float* Zb = g_Z2 + ((size_t)b << 10) * (2*O);

    float4 ctr = *(const float4*)&g_Z2[(size_t)n*(2*O) + O + cg];
    float4 mx = {-FLT_MAX, -FLT_MAX, -FLT_MAX, -FLT_MAX};
    float4 mn = { FLT_MAX,  FLT_MAX,  FLT_MAX,  FLT_MAX};
    float4 s  = {0.f, 0.f, 0.f, 0.f};
    float4 s2 = {0.f, 0.f, 0.f, 0.f};

    #pragma unroll
    for (int j = 0; j < KNN; j++) {
        int m = sidx[p*KNN + j];
        float4 z = *(const float4*)&Zb[(size_t)m*(2*O) + cg];
        mx.x = fmaxf(mx.x, z.x); mn.x = fminf(mn.x, z.x); s.x += z.x; s2.x = fmaf(z.x, z.x, s2.x);
        mx.y = fmaxf(mx.y, z.y); mn.y = fminf(mn.y, z.y); s.y += z.y; s2.y = fmaf(z.y, z.y, s2.y);
        mx.z = fmaxf(mx.z, z.z); mn.z = fminf(mn.z, z.z); s.z += z.z; s2.z = fmaf(z.z, z.z, s2.z);
        mx.w = fmaxf(mx.w, z.w); mn.w = fminf(mn.w, z.w); s.w += z.w; s2.w = fmaf(z.w, z.w, s2.w);
    }

    float4 omx = {mx.x + ctr.x, mx.y + ctr.y, mx.z + ctr.z, mx.w + ctr.w};
    float4 omn = {mn.x + ctr.x, mn.y + ctr.y, mn.z + ctr.z, mn.w + ctr.w};
    *(float4*)&g_YMAX[(size_t)n*O + cg] = omx;
    *(float4*)&g_YMIN[(size_t)n*O + cg] = omn;

    const float KF = (float)KNN;
    atomicAdd(&ssum[cg+0], s.x + KF*ctr.x);
    atomicAdd(&ssum[cg+1], s.y + KF*ctr.y);
    atomicAdd(&ssum[cg+2], s.z + KF*ctr.z);
    atomicAdd(&ssum[cg+3], s.w + KF*ctr.w);
    atomicAdd(&ssq2[cg+0], s2.x + 2.f*ctr.x*s.x + KF*ctr.x*ctr.x);
    atomicAdd(&ssq2[cg+1], s2.y + 2.f*ctr.y*s.y + KF*ctr.y*ctr.y);
    atomicAdd(&ssq2[cg+2], s2.z + 2.f*ctr.z*s.z + KF*ctr.z*ctr.z);
    atomicAdd(&ssq2[cg+3], s2.w + 2.f*ctr.w*s.w + KF*ctr.w*ctr.w);
    __syncthreads();
    if (t < O) {
        atomicAdd(&g_SUM[t],   (double)ssum[t]);
        atomicAdd(&g_SUMSQ[t], (double)ssq2[t]);
    }
}

// ---------------- BN affine coeffs; self-resets accumulators ----------------
__global__ void stats_kernel(const float* __restrict__ g, const float* __restrict__ beta,
                             float count, int O, int resetMM) {
    int o = threadIdx.x;
    if (resetMM) {
        for (int i = o; i < BB*512; i += 512) { g_MXU[i] = 0u; g_MNU[i] = 0xFFFFFFFFu; }
    }
    if (o >= O) return;
    double m   = g_SUM[o]   / (double)count;
    double var = g_SUMSQ[o] / (double)count - m*m;
    float a = g[o] / sqrtf((float)var + 1e-5f);
    g_A[o]  = a;
    g_Cc[o] = beta[o] - (float)m * a;
    g_SUM[o] = 0.0; g_SUMSQ[o] = 0.0;
}

// ---------------- apply norm+lrelu, write concat features + per-point sq ----------------
template<int O>
__global__ void apply_kernel(int outOff) {
    constexpr int PPB = 256 / O;   // 4, 2, 1
    __shared__ float psq[PPB > 0 ? PPB : 1];
    int t = threadIdx.x;
    int p = t / O;
    int o = t - p*O;
    int n = blockIdx.x * PPB + p;
    size_t i = (size_t)n*O + o;

    if (t < PPB) psq[t] = 0.f;
    __syncthreads();

    float a = g_A[o], c = g_Cc[o];
    float sel = (a >= 0.f) ? g_YMAX[i] : g_YMIN[i];
    float v = fmaf(a, sel, c);
    v = (v >= 0.f) ? v : 0.2f*v;
    g_FEAT[(size_t)n*512 + outOff + o] = v;

    float s = v*v;
    #pragma unroll
    for (int sh = 16; sh; sh >>= 1) s += __shfl_down_sync(0xFFFFFFFFu, s, sh);
    if ((t & 31) == 0) atomicAdd(&psq[p], s);
    __syncthreads();
    if (o == 0) g_SQ[n] = psq[p];
}

// ---------------- final norm + global max + embedding ----------------
__global__ void emb_kernel(const float* __restrict__ wemb, float* __restrict__ out) {
    __shared__ float feat[512];
    int b = blockIdx.x, t = threadIdx.x;
    for (int o = t; o < 512; o += 256) {
        float a = g_A[o], c = g_Cc[o];
        float sel = (a >= 0.f) ? decf(g_MXU[b*512 + o]) : decf(g_MNU[b*512 + o]);
        float v = fmaf(a, sel, c);
        feat[o] = (v >= 0.f) ? v : 0.2f*v;
    }
    __syncthreads();
    const float* wr = wemb + (size_t)t * 512;
    float s = 0.f;
    for (int c = 0; c < 512; c++) s = fmaf(wr[c], feat[c], s);
    out[b*256 + t] = s;
}

// ---------------- host orchestration ----------------
template<int C, int O>
static void run_edge_big(const float* feat, int off, const float* wcat,
                         const float* g, const float* beta, int outOff, int resetMM) {
    dim3 gg(36, 1, BB);
    gram_sym<<<gg, 256>>>(feat + off, 512, C);
    topk_kernel<<<BB*NN/8, 256>>>();
    dim3 zg(64, (2*O)/128, 1);
    sgemm128<1><<<zg, 256>>>(feat + off, 512, wcat, C, C, 2*O);
    gather_kernel<O><<<BB*NN/(256/(O/4)), 256>>>();
    stats_kernel<<<1, 512>>>(g, beta, (float)(BB*NN*KNN), O, resetMM);
    apply_kernel<O><<<BB*NN/(256/O), 256>>>(outOff);
}

extern "C" void kernel_launch(void* const* d_in, const int* in_sizes, int n_in,
                              void* d_out, int out_size) {
    (void)in_sizes; (void)n_in; (void)out_size;
    const float* x    = (const float*)d_in[0];
    const float* w1   = (const float*)d_in[1];
    const float* g1   = (const float*)d_in[2];
    const float* b1   = (const float*)d_in[3];
    const float* w2   = (const float*)d_in[4];
    const float* g2   = (const float*)d_in[5];
    const float* b2   = (const float*)d_in[6];
    const float* w3   = (const float*)d_in[7];
    const float* g3   = (const float*)d_in[8];
    const float* b3   = (const float*)d_in[9];
    const float* w4   = (const float*)d_in[10];
    const float* g4   = (const float*)d_in[11];
    const float* b4   = (const float*)d_in[12];
    const float* w5   = (const float*)d_in[13];
    const float* g5   = (const float*)d_in[14];
    const float* b5   = (const float*)d_in[15];
    const float* wemb = (const float*)d_in[16];
    float* out = (float*)d_out;

    float *feat, *wcat;
    cudaGetSymbolAddress((void**)&feat, g_FEAT);
    cudaGetSymbolAddress((void**)&wcat, g_WCAT);

    prep_kernel<<<(90496 + 255)/256, 256>>>(w1, w2, w3, w4);

    // ---- stage 1 (C=3): fused distance + topk, small zgemm ----
    topk1_kernel<<<BB*NN/8, 256>>>(x);
    dim3 zg1(BB*NN/64, 2);
    zgemm_kernel<3, 128><<<zg1, 256>>>(x, 3, 0, wcat);
    gather_kernel<64><<<BB*NN/16, 256>>>();
    stats_kernel<<<1, 512>>>(g1, b1, (float)(BB*NN*KNN), 64, 0);
    apply_kernel<64><<<BB*NN/4, 256>>>(0);   // also writes g_SQ for stage 2

    // ---- stages 2-4: symmetric gram + SGEMM path ----
    run_edge_big<64,  64 >(feat, 0,   wcat + 384,   g2, b2, 64, 0);
    run_edge_big<64,  128>(feat, 64,  wcat + 8576,  g3, b3, 128, 0);
    run_edge_big<128, 256>(feat, 128, wcat + 24960, g4, b4, 256, 1);

    // ---- final conv 512x512 fused with stats + max/min ----
    dim3 g5g(64, 4, 1);
    sgemm128<2><<<g5g, 256>>>(feat, 512, w5, 512, 512, 0);
    stats_kernel<<<1, 512>>>(g5, b5, (float)(BB*NN), 512, 0);
    emb_kernel<<<BB, 256>>>(wemb, out);
}